// round 7
// baseline (speedup 1.0000x reference)
#include <cuda_runtime.h>
#include <cuda_fp16.h>
#include <cstdint>

// Problem shape (fixed)
#define BB 8
#define NN 256
#define DD 128
#define KK 256   // 2*D

// Scratch
__device__ float g_Pi[BB * NN * KK];   // Pi with b1 folded in
__device__ float g_Pj[BB * NN * KK];
__device__ __half g_W2h[DD * KK];      // W2 transposed to [c][k], half

// ---------------------------------------------------------------------------
// Helpers
// ---------------------------------------------------------------------------
__device__ __forceinline__ uint32_t h2_as_u32(__half2 h) {
    union { __half2 h; uint32_t u; } cvt;
    cvt.h = h;
    return cvt.u;
}

// fp16 MMA m16n8k16, fp32 accumulate
__device__ __forceinline__ void mma_f16(float* d,
                                        uint32_t a0, uint32_t a1, uint32_t a2, uint32_t a3,
                                        uint32_t b0, uint32_t b1) {
    asm volatile(
        "mma.sync.aligned.m16n8k16.row.col.f32.f16.f16.f32 "
        "{%0,%1,%2,%3}, {%4,%5,%6,%7}, {%8,%9}, {%0,%1,%2,%3};"
        : "+f"(d[0]), "+f"(d[1]), "+f"(d[2]), "+f"(d[3])
        : "r"(a0), "r"(a1), "r"(a2), "r"(a3), "r"(b0), "r"(b1));
}

// ldmatrix 4x m8n8 b16 tiles
__device__ __forceinline__ void ldx4(uint32_t* r, uint32_t addr) {
    asm volatile(
        "ldmatrix.sync.aligned.m8n8.x4.shared.b16 {%0,%1,%2,%3}, [%4];"
        : "=r"(r[0]), "=r"(r[1]), "=r"(r[2]), "=r"(r[3]) : "r"(addr));
}

// ---------------------------------------------------------------------------
// Tour output
// ---------------------------------------------------------------------------
__global__ void tour_kernel(float* __restrict__ out) {
    int idx = blockIdx.x * 256 + threadIdx.x;
    if (idx < BB * NN) out[idx] = (float)(idx & (NN - 1));
}

// ---------------------------------------------------------------------------
// Projection kernel (fp32 exact)
// ---------------------------------------------------------------------------
__global__ __launch_bounds__(256) void proj_kernel(const float* __restrict__ x,
                                                   const float* __restrict__ W1,
                                                   const float* __restrict__ b1) {
    int blk = blockIdx.x;
    int b   = blk >> 5;
    int n0  = (blk & 31) * 8;

    __shared__ float xs[9][DD];
    for (int t = threadIdx.x; t < 9 * DD; t += 256) {
        int r = t / DD, d = t % DD;
        int n = (n0 + r) & (NN - 1);
        xs[r][d] = x[((size_t)b * NN + n) * DD + d];
    }
    __syncthreads();

    int c = threadIdx.x;
    float accPi[8], accPj[8];
#pragma unroll
    for (int r = 0; r < 8; r++) { accPi[r] = 0.f; accPj[r] = 0.f; }

#pragma unroll 4
    for (int d = 0; d < DD; d++) {
        float wa = W1[(0 * DD + d) * KK + c];
        float wb = W1[(1 * DD + d) * KK + c];
        float wc = W1[(2 * DD + d) * KK + c];
        float wd = W1[(3 * DD + d) * KK + c];
#pragma unroll
        for (int r = 0; r < 8; r++) {
            float xv  = xs[r][d];
            float xnv = xs[r + 1][d];
            accPi[r] += xv * wa + xnv * wb;
            accPj[r] += xv * wc + xnv * wd;
        }
    }
    float b1c = b1[c];
#pragma unroll
    for (int r = 0; r < 8; r++) {
        int n = n0 + r;
        size_t off = ((size_t)b * NN + n) * KK + c;
        g_Pi[off] = accPi[r] + b1c;
        g_Pj[off] = accPj[r];
    }
}

// ---------------------------------------------------------------------------
// W2 prep: transpose [k][c] fp32 -> [c][k] half
// ---------------------------------------------------------------------------
__global__ void w2prep_kernel(const float* __restrict__ W2) {
    int idx = blockIdx.x * 256 + threadIdx.x;  // k*128 + c
    int k = idx >> 7, c = idx & 127;
    g_W2h[c * KK + k] = __float2half_rn(W2[idx]);
}

// ---------------------------------------------------------------------------
// Pair kernel: CTA = (b, {i0,i0+1}, j-tile of 128), fp16 m16n8k16.
// 512 thr = 16 warps: wy=wid&3 -> j 32-range, wx=(wid>>2)&3 -> c 32-range.
// Each warp handles BOTH i's (shares B fragments). ldmatrix fragment loads.
// W2 (half, [c][k], stride 264) fully SMEM-resident. A double buffered.
// ---------------------------------------------------------------------------
#define BROW 264                       // B smem row stride (halves): 256+8
#define AROW 24                        // A smem row stride (halves): 16+8

// byte offsets in dynamic smem
#define OFF_BH   0                     // 128*264*2      = 67584
#define OFF_AH   67584                 // 2*2*128*24*2   = 24576
#define OFF_PI   92160                 // 512*4          = 2048
#define OFF_B2   94208                 // 512
#define OFF_W3   94720                 // 512
#define OFF_RED  95232                 // 2*128*4*4      = 4096
#define SMEM_BYTES 99328

__global__ __launch_bounds__(512) void pair_kernel(const float* __restrict__ b2g,
                                                   const float* __restrict__ w3g,
                                                   const float* __restrict__ b3g,
                                                   float* __restrict__ outm) {
    extern __shared__ char smem[];
    __half* Bh  = (__half*)(smem + OFF_BH);
    __half* Ah  = (__half*)(smem + OFF_AH);
    float*  PiS = (float*)(smem + OFF_PI);
    float*  b2s = (float*)(smem + OFF_B2);
    float*  w3s = (float*)(smem + OFF_W3);
    float*  red = (float*)(smem + OFF_RED);

    int tid  = threadIdx.x;
    int lane = tid & 31, wid = tid >> 5;
    int wy = wid & 3, wx = (wid >> 2) & 3;
    int g  = lane >> 2, tg = lane & 3;

    int bid = blockIdx.x;
    int jt = bid & 1;
    int ig = (bid >> 1) & 127;
    int b  = bid >> 8;
    int j0 = jt << 7, i0 = ig << 1;
    if (i0 > j0 + 125) return;         // fully masked tile (output zeroed by memset)

    const float* Pjb = &g_Pj[(size_t)(b * NN + j0) * KK];

    // Prologue: W2 half image, Pi rows (i0 & i0+1 contiguous), b2, W3
    {
        const uint4* wsrc = (const uint4*)g_W2h;
#pragma unroll
        for (int q = tid; q < 128 * 32; q += 512) {
            int cc = q >> 5, qq = q & 31;
            *(uint4*)&Bh[cc * BROW + qq * 8] = wsrc[cc * 32 + qq];
        }
        const float* pi0 = &g_Pi[(size_t)(b * NN + i0) * KK];
        PiS[tid] = pi0[tid];                       // 512 = 2 rows x 256
        if (tid < 128) { b2s[tid] = b2g[tid]; w3s[tid] = w3g[tid]; }
    }

    float acc[2][2][4][4];
#pragma unroll
    for (int i = 0; i < 2; i++)
#pragma unroll
        for (int m = 0; m < 2; m++)
#pragma unroll
            for (int n = 0; n < 4; n++)
#pragma unroll
                for (int q = 0; q < 4; q++) acc[i][m][n][q] = 0.f;

    // A staging mapping: thread -> (row jA, i iS, k-range kqS..kqS+7)
    int jA  = tid & 127;
    int iS  = (tid >> 7) & 1;
    int kqS = (tid >> 8) << 3;
    const float* PjRow = &Pjb[(size_t)jA * KK + kqS];
    const float* PiRow = &PiS[iS * 256 + kqS];

    // Load chunk 0 Pj into regs
    float4 pj0 = *(const float4*)&PjRow[0];
    float4 pj1 = *(const float4*)&PjRow[4];

    __syncthreads();   // PiS ready

    // Store chunk 0 into buf 0
    {
        __half2 h0 = __floats2half2_rn(fmaxf(pj0.x + PiRow[0], 0.f), fmaxf(pj0.y + PiRow[1], 0.f));
        __half2 h1 = __floats2half2_rn(fmaxf(pj0.z + PiRow[2], 0.f), fmaxf(pj0.w + PiRow[3], 0.f));
        __half2 h2 = __floats2half2_rn(fmaxf(pj1.x + PiRow[4], 0.f), fmaxf(pj1.y + PiRow[5], 0.f));
        __half2 h3 = __floats2half2_rn(fmaxf(pj1.z + PiRow[6], 0.f), fmaxf(pj1.w + PiRow[7], 0.f));
        uint4 v;
        v.x = h2_as_u32(h0); v.y = h2_as_u32(h1);
        v.z = h2_as_u32(h2); v.w = h2_as_u32(h3);
        *(uint4*)&Ah[(iS * 128 + jA) * AROW + kqS] = v;
    }
    __syncthreads();

    // ldmatrix lane addresses (bytes)
    uint32_t AhAddr = (uint32_t)__cvta_generic_to_shared(Ah);
    uint32_t BhAddr = (uint32_t)__cvta_generic_to_shared(Bh);
    int rowL = lane & 15, kL = (lane >> 4) * 8;
    uint32_t aLane  = (uint32_t)((wy * 32 + rowL) * AROW + kL) * 2 + AhAddr;
    uint32_t bLane0 = (uint32_t)((wx * 32 + rowL) * BROW + kL) * 2 + BhAddr;
    uint32_t bLane1 = bLane0 + 16 * BROW * 2;

    for (int c = 0; c < 16; c++) {
        int buf = c & 1;
        int k0 = c << 4;
        // Prefetch next Pj chunk
        if (c < 15) {
            pj0 = *(const float4*)&PjRow[k0 + 16];
            pj1 = *(const float4*)&PjRow[k0 + 20];
        }

        // B fragments for this chunk: 2x ldmatrix.x4 covering 4 n-octets
        uint32_t bq0[4], bq1[4];
        ldx4(bq0, bLane0 + (uint32_t)k0 * 2);
        ldx4(bq1, bLane1 + (uint32_t)k0 * 2);

        // Compute: for each i, each m-half, one A ldmatrix.x4 + 4 MMAs
#pragma unroll
        for (int i = 0; i < 2; i++) {
#pragma unroll
            for (int mh = 0; mh < 2; mh++) {
                uint32_t a[4];
                ldx4(a, aLane + (uint32_t)(((buf * 2 + i) * 128 + mh * 16) * AROW) * 2);
                mma_f16(acc[i][mh][0], a[0], a[1], a[2], a[3], bq0[0], bq0[2]);
                mma_f16(acc[i][mh][1], a[0], a[1], a[2], a[3], bq0[1], bq0[3]);
                mma_f16(acc[i][mh][2], a[0], a[1], a[2], a[3], bq1[0], bq1[2]);
                mma_f16(acc[i][mh][3], a[0], a[1], a[2], a[3], bq1[1], bq1[3]);
            }
        }

        // Store chunk c+1 into the other buffer
        if (c < 15) {
            int nb = buf ^ 1;
            const float* pb = PiRow + k0 + 16;
            __half2 h0 = __floats2half2_rn(fmaxf(pj0.x + pb[0], 0.f), fmaxf(pj0.y + pb[1], 0.f));
            __half2 h1 = __floats2half2_rn(fmaxf(pj0.z + pb[2], 0.f), fmaxf(pj0.w + pb[3], 0.f));
            __half2 h2 = __floats2half2_rn(fmaxf(pj1.x + pb[4], 0.f), fmaxf(pj1.y + pb[5], 0.f));
            __half2 h3 = __floats2half2_rn(fmaxf(pj1.z + pb[6], 0.f), fmaxf(pj1.w + pb[7], 0.f));
            uint4 v;
            v.x = h2_as_u32(h0); v.y = h2_as_u32(h1);
            v.z = h2_as_u32(h2); v.w = h2_as_u32(h3);
            *(uint4*)&Ah[((nb * 2 + iS) * 128 + jA) * AROW + kqS] = v;
        }
        __syncthreads();
    }

    // Epilogue: relu(C+b2).W3 partial dots, shfl reduce over tg, smem reduce over wx
    float b3v = b3g[0];
#pragma unroll
    for (int i = 0; i < 2; i++) {
#pragma unroll
        for (int m = 0; m < 2; m++) {
            float s0 = 0.f, s1 = 0.f;
#pragma unroll
            for (int n = 0; n < 4; n++) {
                int c0 = wx * 32 + n * 8 + tg * 2;
                float bA  = b2s[c0],     wA  = w3s[c0];
                float bBv = b2s[c0 + 1], wBv = w3s[c0 + 1];
                s0 += fmaxf(acc[i][m][n][0] + bA, 0.f) * wA
                    + fmaxf(acc[i][m][n][1] + bBv, 0.f) * wBv;
                s1 += fmaxf(acc[i][m][n][2] + bA, 0.f) * wA
                    + fmaxf(acc[i][m][n][3] + bBv, 0.f) * wBv;
            }
            s0 += __shfl_xor_sync(0xffffffffu, s0, 1);
            s0 += __shfl_xor_sync(0xffffffffu, s0, 2);
            s1 += __shfl_xor_sync(0xffffffffu, s1, 1);
            s1 += __shfl_xor_sync(0xffffffffu, s1, 2);
            if (tg == 0) {
                int r0 = wy * 32 + m * 16 + g;
                red[(i * 128 + r0) * 4 + wx]     = s0;
                red[(i * 128 + r0 + 8) * 4 + wx] = s1;
            }
        }
    }
    __syncthreads();

    if (tid < 256) {
        int i  = tid >> 7;
        int jj = tid & 127;
        const float* rp = &red[(i * 128 + jj) * 4];
        float sum = rp[0] + rp[1] + rp[2] + rp[3] + b3v;
        int iG = i0 + i, j = j0 + jj;
        bool valid = (j >= iG + 2) && ((j - iG) != (NN - 1));
        outm[((size_t)(b * NN + iG)) * NN + j] = valid ? tanhf(sum) : 0.f;
    }
}

// ---------------------------------------------------------------------------
// Launcher
// ---------------------------------------------------------------------------
extern "C" void kernel_launch(void* const* d_in, const int* in_sizes, int n_in,
                              void* d_out, int out_size) {
    const float* x  = (const float*)d_in[0];
    const float* W1 = (const float*)d_in[1];
    const float* b1 = (const float*)d_in[2];
    const float* W2 = (const float*)d_in[3];
    const float* b2 = (const float*)d_in[4];
    const float* W3 = (const float*)d_in[5];
    const float* b3 = (const float*)d_in[6];
    float* out = (float*)d_out;

    const int MAT  = BB * NN * NN;   // 524288
    const int TOUR = BB * NN;        // 2048

    size_t matOff = 0;
    bool hasTour = false;
    if (out_size >= MAT + TOUR) { hasTour = true; matOff = (size_t)out_size - MAT; }

    cudaFuncSetAttribute(pair_kernel, cudaFuncAttributeMaxDynamicSharedMemorySize,
                         SMEM_BYTES);

    cudaMemsetAsync(d_out, 0, (size_t)out_size * sizeof(float), 0);
    if (hasTour) tour_kernel<<<(TOUR + 255) / 256, 256>>>(out);

    proj_kernel<<<256, 256>>>(x, W1, b1);
    w2prep_kernel<<<128, 256>>>(W2);
    pair_kernel<<<BB * 128 * 2, 512, SMEM_BYTES>>>(b2, W3, b3, out + matOff);
}

// round 8
// speedup vs baseline: 1.7627x; 1.7627x over previous
#include <cuda_runtime.h>
#include <cuda_fp16.h>
#include <cstdint>

// Problem shape (fixed)
#define BB 8
#define NN 256
#define DD 128
#define KK 256   // 2*D

// Scratch (half precision: mantissa identical to tf32; range is safe, O(1) data)
__device__ __half g_Pih[BB * NN * KK];   // Pi with b1 folded in
__device__ __half g_Pjh[BB * NN * KK];
__device__ __half g_W2h[DD * KK];        // W2 transposed to [c][k]

// ---------------------------------------------------------------------------
// Helpers
// ---------------------------------------------------------------------------
__device__ __forceinline__ uint32_t h2_as_u32(__half2 h) {
    union { __half2 h; uint32_t u; } cvt;
    cvt.h = h;
    return cvt.u;
}

// fp16 MMA m16n8k16, fp32 accumulate
__device__ __forceinline__ void mma_f16(float* d,
                                        uint32_t a0, uint32_t a1, uint32_t a2, uint32_t a3,
                                        uint32_t b0, uint32_t b1) {
    asm volatile(
        "mma.sync.aligned.m16n8k16.row.col.f32.f16.f16.f32 "
        "{%0,%1,%2,%3}, {%4,%5,%6,%7}, {%8,%9}, {%0,%1,%2,%3};"
        : "+f"(d[0]), "+f"(d[1]), "+f"(d[2]), "+f"(d[3])
        : "r"(a0), "r"(a1), "r"(a2), "r"(a3), "r"(b0), "r"(b1));
}

// ldmatrix 4x m8n8 b16 tiles
__device__ __forceinline__ void ldx4(uint32_t* r, uint32_t addr) {
    asm volatile(
        "ldmatrix.sync.aligned.m8n8.x4.shared.b16 {%0,%1,%2,%3}, [%4];"
        : "=r"(r[0]), "=r"(r[1]), "=r"(r[2]), "=r"(r[3]) : "r"(addr));
}

// ---------------------------------------------------------------------------
// Tour output
// ---------------------------------------------------------------------------
__global__ void tour_kernel(float* __restrict__ out) {
    int idx = blockIdx.x * 256 + threadIdx.x;
    if (idx < BB * NN) out[idx] = (float)(idx & (NN - 1));
}

// ---------------------------------------------------------------------------
// Projection kernel (fp32 math, half output)
// ---------------------------------------------------------------------------
__global__ __launch_bounds__(256) void proj_kernel(const float* __restrict__ x,
                                                   const float* __restrict__ W1,
                                                   const float* __restrict__ b1) {
    int blk = blockIdx.x;
    int b   = blk >> 5;
    int n0  = (blk & 31) * 8;

    __shared__ float xs[9][DD];
    for (int t = threadIdx.x; t < 9 * DD; t += 256) {
        int r = t / DD, d = t % DD;
        int n = (n0 + r) & (NN - 1);
        xs[r][d] = x[((size_t)b * NN + n) * DD + d];
    }
    __syncthreads();

    int c = threadIdx.x;
    float accPi[8], accPj[8];
#pragma unroll
    for (int r = 0; r < 8; r++) { accPi[r] = 0.f; accPj[r] = 0.f; }

#pragma unroll 4
    for (int d = 0; d < DD; d++) {
        float wa = W1[(0 * DD + d) * KK + c];
        float wb = W1[(1 * DD + d) * KK + c];
        float wc = W1[(2 * DD + d) * KK + c];
        float wd = W1[(3 * DD + d) * KK + c];
#pragma unroll
        for (int r = 0; r < 8; r++) {
            float xv  = xs[r][d];
            float xnv = xs[r + 1][d];
            accPi[r] += xv * wa + xnv * wb;
            accPj[r] += xv * wc + xnv * wd;
        }
    }
    float b1c = b1[c];
#pragma unroll
    for (int r = 0; r < 8; r++) {
        int n = n0 + r;
        size_t off = ((size_t)b * NN + n) * KK + c;
        g_Pih[off] = __float2half_rn(accPi[r] + b1c);
        g_Pjh[off] = __float2half_rn(accPj[r]);
    }
}

// ---------------------------------------------------------------------------
// W2 prep: transpose [k][c] fp32 -> [c][k] half
// ---------------------------------------------------------------------------
__global__ void w2prep_kernel(const float* __restrict__ W2) {
    int idx = blockIdx.x * 256 + threadIdx.x;  // k*128 + c
    int k = idx >> 7, c = idx & 127;
    g_W2h[c * KK + k] = __float2half_rn(W2[idx]);
}

// ---------------------------------------------------------------------------
// Pair kernel: CTA = (b, {i0,i0+1}, j-tile of 128), fp16 m16n8k16.
// 256 thr = 8 warps: wy=wid&3 -> j 32-range, wx=wid>>2 -> c 64-range.
// Both W2 [c][k] and the Pj j-tile [j][k] live in SMEM (half, stride 264).
// A-fragments are built IN REGISTERS (hadd2+hmax2) from raw LDS reads at the
// fragment coordinates -> no staging, no double buffer, NO syncs in the K loop.
// Pj fragment loads are shared across both i's.
// ---------------------------------------------------------------------------
#define BROW 264                       // half stride: 256+8 (conflict-free)

// byte offsets in dynamic smem
#define OFF_BH   0                     // 128*264*2 = 67584
#define OFF_PJ   67584                 // 128*264*2 = 67584
#define OFF_PI   135168                // 512*2     = 1024
#define OFF_B2   136192                // 512
#define OFF_W3   136704                // 512
#define OFF_RED  137216                // 2*128*2*4 = 2048
#define SMEM_BYTES 139264

__global__ __launch_bounds__(256, 1) void pair_kernel(const float* __restrict__ b2g,
                                                      const float* __restrict__ w3g,
                                                      const float* __restrict__ b3g,
                                                      float* __restrict__ outm) {
    extern __shared__ char smem[];
    __half* Bh  = (__half*)(smem + OFF_BH);
    __half* Pjs = (__half*)(smem + OFF_PJ);
    __half* Pis = (__half*)(smem + OFF_PI);
    float*  b2s = (float*)(smem + OFF_B2);
    float*  w3s = (float*)(smem + OFF_W3);
    float*  red = (float*)(smem + OFF_RED);

    int tid  = threadIdx.x;
    int lane = tid & 31, wid = tid >> 5;
    int wy = wid & 3, wx = wid >> 2;
    int g  = lane >> 2, tg = lane & 3;

    int bid = blockIdx.x;
    int jt = bid & 1;
    int ig = (bid >> 1) & 127;
    int b  = bid >> 8;
    int j0 = jt << 7, i0 = ig << 1;
    if (i0 > j0 + 125) return;         // fully masked tile (output zeroed by memset)

    // Prologue: W2 image, Pj j-tile, Pi rows, b2, W3
    {
        const uint4* wsrc = (const uint4*)g_W2h;
#pragma unroll
        for (int q = tid; q < 4096; q += 256) {
            int cc = q >> 5, qq = q & 31;
            *(uint4*)&Bh[cc * BROW + qq * 8] = wsrc[cc * 32 + qq];
        }
        const uint4* psrc = (const uint4*)&g_Pjh[(size_t)(b * NN + j0) * KK];
#pragma unroll
        for (int q = tid; q < 4096; q += 256) {
            int jj = q >> 5, qq = q & 31;
            *(uint4*)&Pjs[jj * BROW + qq * 8] = psrc[jj * 32 + qq];
        }
        const __half* pisrc = &g_Pih[(size_t)(b * NN + i0) * KK];
        Pis[tid]       = pisrc[tid];
        Pis[256 + tid] = pisrc[256 + tid];
        if (tid < 128) { b2s[tid] = b2g[tid]; w3s[tid] = w3g[tid]; }
    }
    __syncthreads();   // the only barrier before the epilogue

    float acc[2][2][8][4];
#pragma unroll
    for (int i = 0; i < 2; i++)
#pragma unroll
        for (int m = 0; m < 2; m++)
#pragma unroll
            for (int n = 0; n < 8; n++)
#pragma unroll
                for (int q = 0; q < 4; q++) acc[i][m][n][q] = 0.f;

    // ldmatrix lane addresses for B (bytes)
    uint32_t BhAddr = (uint32_t)__cvta_generic_to_shared(Bh);
    int rowL = lane & 15, kL = (lane >> 4) * 8;
    uint32_t bAddr[4];
#pragma unroll
    for (int t = 0; t < 4; t++)
        bAddr[t] = (uint32_t)((wx * 64 + t * 16 + rowL) * BROW + kL) * 2 + BhAddr;

    const __half2 zero2 = __float2half2_rn(0.f);

    for (int c = 0; c < 16; c++) {
        int k0 = c << 4;

        // B fragments: 4x ldmatrix.x4 -> 8 (b0,b1) pairs covering 64 c
        uint32_t bq[4][4];
#pragma unroll
        for (int t = 0; t < 4; t++) ldx4(bq[t], bAddr[t] + (uint32_t)k0 * 2);

        // Pi half2 per i (broadcast loads)
        __half2 pil[2], pih[2];
#pragma unroll
        for (int i = 0; i < 2; i++) {
            pil[i] = *(const __half2*)&Pis[i * 256 + k0 + 2 * tg];
            pih[i] = *(const __half2*)&Pis[i * 256 + k0 + 2 * tg + 8];
        }

#pragma unroll
        for (int mh = 0; mh < 2; mh++) {
            int row = wy * 32 + mh * 16 + g;
            // Pj fragment loads (shared across both i's)
            __half2 pjA = *(const __half2*)&Pjs[row * BROW + k0 + 2 * tg];
            __half2 pjB = *(const __half2*)&Pjs[(row + 8) * BROW + k0 + 2 * tg];
            __half2 pjC = *(const __half2*)&Pjs[row * BROW + k0 + 2 * tg + 8];
            __half2 pjD = *(const __half2*)&Pjs[(row + 8) * BROW + k0 + 2 * tg + 8];
#pragma unroll
            for (int i = 0; i < 2; i++) {
                uint32_t a0 = h2_as_u32(__hmax2(__hadd2(pjA, pil[i]), zero2));
                uint32_t a1 = h2_as_u32(__hmax2(__hadd2(pjB, pil[i]), zero2));
                uint32_t a2 = h2_as_u32(__hmax2(__hadd2(pjC, pih[i]), zero2));
                uint32_t a3 = h2_as_u32(__hmax2(__hadd2(pjD, pih[i]), zero2));
#pragma unroll
                for (int t = 0; t < 4; t++) {
                    mma_f16(acc[i][mh][2 * t],     a0, a1, a2, a3, bq[t][0], bq[t][2]);
                    mma_f16(acc[i][mh][2 * t + 1], a0, a1, a2, a3, bq[t][1], bq[t][3]);
                }
            }
        }
    }

    // Epilogue: relu(C+b2).W3 partial dots, shfl reduce over tg, smem over wx
    float b3v = b3g[0];
#pragma unroll
    for (int i = 0; i < 2; i++) {
#pragma unroll
        for (int m = 0; m < 2; m++) {
            float s0 = 0.f, s1 = 0.f;
#pragma unroll
            for (int n = 0; n < 8; n++) {
                int c0 = wx * 64 + n * 8 + tg * 2;
                float bA  = b2s[c0],     wA  = w3s[c0];
                float bBv = b2s[c0 + 1], wBv = w3s[c0 + 1];
                s0 += fmaxf(acc[i][m][n][0] + bA, 0.f) * wA
                    + fmaxf(acc[i][m][n][1] + bBv, 0.f) * wBv;
                s1 += fmaxf(acc[i][m][n][2] + bA, 0.f) * wA
                    + fmaxf(acc[i][m][n][3] + bBv, 0.f) * wBv;
            }
            s0 += __shfl_xor_sync(0xffffffffu, s0, 1);
            s0 += __shfl_xor_sync(0xffffffffu, s0, 2);
            s1 += __shfl_xor_sync(0xffffffffu, s1, 1);
            s1 += __shfl_xor_sync(0xffffffffu, s1, 2);
            if (tg == 0) {
                int r0 = wy * 32 + m * 16 + g;
                red[(i * 128 + r0) * 2 + wx]     = s0;
                red[(i * 128 + r0 + 8) * 2 + wx] = s1;
            }
        }
    }
    __syncthreads();

    {
        int i  = tid >> 7;
        int jj = tid & 127;
        const float* rp = &red[(i * 128 + jj) * 2];
        float sum = rp[0] + rp[1] + b3v;
        int iG = i0 + i, j = j0 + jj;
        bool valid = (j >= iG + 2) && ((j - iG) != (NN - 1));
        outm[((size_t)(b * NN + iG)) * NN + j] = valid ? tanhf(sum) : 0.f;
    }
}

// ---------------------------------------------------------------------------
// Launcher
// ---------------------------------------------------------------------------
extern "C" void kernel_launch(void* const* d_in, const int* in_sizes, int n_in,
                              void* d_out, int out_size) {
    const float* x  = (const float*)d_in[0];
    const float* W1 = (const float*)d_in[1];
    const float* b1 = (const float*)d_in[2];
    const float* W2 = (const float*)d_in[3];
    const float* b2 = (const float*)d_in[4];
    const float* W3 = (const float*)d_in[5];
    const float* b3 = (const float*)d_in[6];
    float* out = (float*)d_out;

    const int MAT  = BB * NN * NN;   // 524288
    const int TOUR = BB * NN;        // 2048

    size_t matOff = 0;
    bool hasTour = false;
    if (out_size >= MAT + TOUR) { hasTour = true; matOff = (size_t)out_size - MAT; }

    cudaFuncSetAttribute(pair_kernel, cudaFuncAttributeMaxDynamicSharedMemorySize,
                         SMEM_BYTES);

    cudaMemsetAsync(d_out, 0, (size_t)out_size * sizeof(float), 0);
    if (hasTour) tour_kernel<<<(TOUR + 255) / 256, 256>>>(out);

    proj_kernel<<<256, 256>>>(x, W1, b1);
    w2prep_kernel<<<128, 256>>>(W2);
    pair_kernel<<<BB * 128 * 2, 256, SMEM_BYTES>>>(b2, W3, b3, out + matOff);
}

// round 9
// speedup vs baseline: 1.7976x; 1.0198x over previous
#include <cuda_runtime.h>
#include <cuda_fp16.h>
#include <cstdint>

// Problem shape (fixed)
#define BB 8
#define NN 256
#define DD 128
#define KK 256   // 2*D

// Scratch (half: mantissa == tf32, range safe for O(1) data)
__device__ __half g_Pih[BB * NN * KK];   // Pi with b1 folded in
__device__ __half g_Pjh[BB * NN * KK];
__device__ __half g_W2h[DD * KK];        // W2 transposed to [c][k]

// ---------------------------------------------------------------------------
// Helpers
// ---------------------------------------------------------------------------
__device__ __forceinline__ uint32_t h2_as_u32(__half2 h) {
    union { __half2 h; uint32_t u; } cvt;
    cvt.h = h;
    return cvt.u;
}

// fp16 MMA m16n8k16, fp32 accumulate
__device__ __forceinline__ void mma_f16(float* d,
                                        uint32_t a0, uint32_t a1, uint32_t a2, uint32_t a3,
                                        uint32_t b0, uint32_t b1) {
    asm volatile(
        "mma.sync.aligned.m16n8k16.row.col.f32.f16.f16.f32 "
        "{%0,%1,%2,%3}, {%4,%5,%6,%7}, {%8,%9}, {%0,%1,%2,%3};"
        : "+f"(d[0]), "+f"(d[1]), "+f"(d[2]), "+f"(d[3])
        : "r"(a0), "r"(a1), "r"(a2), "r"(a3), "r"(b0), "r"(b1));
}

// ldmatrix 4x m8n8 b16 tiles
__device__ __forceinline__ void ldx4(uint32_t* r, uint32_t addr) {
    asm volatile(
        "ldmatrix.sync.aligned.m8n8.x4.shared.b16 {%0,%1,%2,%3}, [%4];"
        : "=r"(r[0]), "=r"(r[1]), "=r"(r[2]), "=r"(r[3]) : "r"(addr));
}

// ---------------------------------------------------------------------------
// Tour output
// ---------------------------------------------------------------------------
__global__ void tour_kernel(float* __restrict__ out) {
    int idx = blockIdx.x * 256 + threadIdx.x;
    if (idx < BB * NN) out[idx] = (float)(idx & (NN - 1));
}

// ---------------------------------------------------------------------------
// Projection kernel (fp32 math, half output)
// ---------------------------------------------------------------------------
__global__ __launch_bounds__(256) void proj_kernel(const float* __restrict__ x,
                                                   const float* __restrict__ W1,
                                                   const float* __restrict__ b1) {
    int blk = blockIdx.x;
    int b   = blk >> 5;
    int n0  = (blk & 31) * 8;

    __shared__ float xs[9][DD];
    for (int t = threadIdx.x; t < 9 * DD; t += 256) {
        int r = t / DD, d = t % DD;
        int n = (n0 + r) & (NN - 1);
        xs[r][d] = x[((size_t)b * NN + n) * DD + d];
    }
    __syncthreads();

    int c = threadIdx.x;
    float accPi[8], accPj[8];
#pragma unroll
    for (int r = 0; r < 8; r++) { accPi[r] = 0.f; accPj[r] = 0.f; }

#pragma unroll 4
    for (int d = 0; d < DD; d++) {
        float wa = W1[(0 * DD + d) * KK + c];
        float wb = W1[(1 * DD + d) * KK + c];
        float wc = W1[(2 * DD + d) * KK + c];
        float wd = W1[(3 * DD + d) * KK + c];
#pragma unroll
        for (int r = 0; r < 8; r++) {
            float xv  = xs[r][d];
            float xnv = xs[r + 1][d];
            accPi[r] += xv * wa + xnv * wb;
            accPj[r] += xv * wc + xnv * wd;
        }
    }
    float b1c = b1[c];
#pragma unroll
    for (int r = 0; r < 8; r++) {
        int n = n0 + r;
        size_t off = ((size_t)b * NN + n) * KK + c;
        g_Pih[off] = __float2half_rn(accPi[r] + b1c);
        g_Pjh[off] = __float2half_rn(accPj[r]);
    }
}

// ---------------------------------------------------------------------------
// W2 prep: transpose [k][c] fp32 -> [c][k] half
// ---------------------------------------------------------------------------
__global__ void w2prep_kernel(const float* __restrict__ W2) {
    int idx = blockIdx.x * 256 + threadIdx.x;  // k*128 + c
    int k = idx >> 7, c = idx & 127;
    g_W2h[c * KK + k] = __float2half_rn(W2[idx]);
}

// ---------------------------------------------------------------------------
// Pair kernel: CTA = (b, {i0,i0+1}, j-tile of 128), fp16 m16n8k16.
// 512 thr = 16 warps = 2(i) x 4(wy: j 32-range) x 2(wx: c 64-range).
// Each warp: 32j x 64c tile for ONE i -> acc = 64 floats -> <=128 regs
// -> 4 warps/SMSP to hide the LDS->hadd2->hmax2->HMMA chain.
// W2 [c][k] and Pj j-tile [j][k] SMEM-resident (half, stride 264).
// A-fragments built in registers; NO barriers in the K loop.
// ---------------------------------------------------------------------------
#define BROW 264                       // half stride: 256+8 (conflict-free)

// byte offsets in dynamic smem
#define OFF_BH   0                     // 128*264*2 = 67584
#define OFF_PJ   67584                 // 128*264*2 = 67584
#define OFF_PI   135168                // 512*2     = 1024
#define OFF_B2   136192                // 512
#define OFF_W3   136704                // 512
#define OFF_RED  137216                // 2*128*2*4 = 2048
#define SMEM_BYTES 139264

__global__ __launch_bounds__(512, 1) void pair_kernel(const float* __restrict__ b2g,
                                                      const float* __restrict__ w3g,
                                                      const float* __restrict__ b3g,
                                                      float* __restrict__ outm) {
    extern __shared__ char smem[];
    __half* Bh  = (__half*)(smem + OFF_BH);
    __half* Pjs = (__half*)(smem + OFF_PJ);
    __half* Pis = (__half*)(smem + OFF_PI);
    float*  b2s = (float*)(smem + OFF_B2);
    float*  w3s = (float*)(smem + OFF_W3);
    float*  red = (float*)(smem + OFF_RED);

    int tid  = threadIdx.x;
    int lane = tid & 31, wid = tid >> 5;
    int iW = wid & 1;                  // which i this warp handles
    int wy = (wid >> 1) & 3;           // j 32-range
    int wx = wid >> 3;                 // c 64-range (0..1)
    int g  = lane >> 2, tg = lane & 3;

    int bid = blockIdx.x;
    int jt = bid & 1;
    int ig = (bid >> 1) & 127;
    int b  = bid >> 8;
    int j0 = jt << 7, i0 = ig << 1;
    if (i0 > j0 + 125) return;         // fully masked tile (output zeroed by memset)

    // Prologue: W2 image, Pj j-tile, Pi rows, b2, W3
    {
        const uint4* wsrc = (const uint4*)g_W2h;
#pragma unroll
        for (int q = tid; q < 4096; q += 512) {
            int cc = q >> 5, qq = q & 31;
            *(uint4*)&Bh[cc * BROW + qq * 8] = wsrc[cc * 32 + qq];
        }
        const uint4* psrc = (const uint4*)&g_Pjh[(size_t)(b * NN + j0) * KK];
#pragma unroll
        for (int q = tid; q < 4096; q += 512) {
            int jj = q >> 5, qq = q & 31;
            *(uint4*)&Pjs[jj * BROW + qq * 8] = psrc[jj * 32 + qq];
        }
        const __half* pisrc = &g_Pih[(size_t)(b * NN + i0) * KK];
        Pis[tid] = pisrc[tid];          // 512 halves = both i rows
        if (tid < 128) { b2s[tid] = b2g[tid]; w3s[tid] = w3g[tid]; }
    }
    __syncthreads();   // the only barrier before the epilogue

    float acc[2][8][4];
#pragma unroll
    for (int m = 0; m < 2; m++)
#pragma unroll
        for (int n = 0; n < 8; n++)
#pragma unroll
            for (int q = 0; q < 4; q++) acc[m][n][q] = 0.f;

    // ldmatrix lane addresses for B (bytes)
    uint32_t BhAddr = (uint32_t)__cvta_generic_to_shared(Bh);
    int rowL = lane & 15, kL = (lane >> 4) * 8;
    uint32_t bAddr[4];
#pragma unroll
    for (int t = 0; t < 4; t++)
        bAddr[t] = (uint32_t)((wx * 64 + t * 16 + rowL) * BROW + kL) * 2 + BhAddr;

    const __half2 zero2 = __float2half2_rn(0.f);
    const __half* PiRow = &Pis[iW * 256];

    for (int c = 0; c < 16; c++) {
        int k0 = c << 4;

        // B fragments: 4x ldmatrix.x4 -> 8 (b0,b1) pairs covering 64 c
        uint32_t bq[4][4];
#pragma unroll
        for (int t = 0; t < 4; t++) ldx4(bq[t], bAddr[t] + (uint32_t)k0 * 2);

        // Pi half2 (broadcast loads, this warp's i only)
        __half2 pil = *(const __half2*)&PiRow[k0 + 2 * tg];
        __half2 pih = *(const __half2*)&PiRow[k0 + 2 * tg + 8];

#pragma unroll
        for (int mh = 0; mh < 2; mh++) {
            int row = wy * 32 + mh * 16 + g;
            __half2 pjA = *(const __half2*)&Pjs[row * BROW + k0 + 2 * tg];
            __half2 pjB = *(const __half2*)&Pjs[(row + 8) * BROW + k0 + 2 * tg];
            __half2 pjC = *(const __half2*)&Pjs[row * BROW + k0 + 2 * tg + 8];
            __half2 pjD = *(const __half2*)&Pjs[(row + 8) * BROW + k0 + 2 * tg + 8];
            uint32_t a0 = h2_as_u32(__hmax2(__hadd2(pjA, pil), zero2));
            uint32_t a1 = h2_as_u32(__hmax2(__hadd2(pjB, pil), zero2));
            uint32_t a2 = h2_as_u32(__hmax2(__hadd2(pjC, pih), zero2));
            uint32_t a3 = h2_as_u32(__hmax2(__hadd2(pjD, pih), zero2));
#pragma unroll
            for (int t = 0; t < 4; t++) {
                mma_f16(acc[mh][2 * t],     a0, a1, a2, a3, bq[t][0], bq[t][2]);
                mma_f16(acc[mh][2 * t + 1], a0, a1, a2, a3, bq[t][1], bq[t][3]);
            }
        }
    }

    // Epilogue: relu(C+b2).W3 partial dots, shfl reduce over tg, smem over wx
    float b3v = b3g[0];
#pragma unroll
    for (int m = 0; m < 2; m++) {
        float s0 = 0.f, s1 = 0.f;
#pragma unroll
        for (int n = 0; n < 8; n++) {
            int c0 = wx * 64 + n * 8 + tg * 2;
            float bA  = b2s[c0],     wA  = w3s[c0];
            float bBv = b2s[c0 + 1], wBv = w3s[c0 + 1];
            s0 += fmaxf(acc[m][n][0] + bA, 0.f) * wA
                + fmaxf(acc[m][n][1] + bBv, 0.f) * wBv;
            s1 += fmaxf(acc[m][n][2] + bA, 0.f) * wA
                + fmaxf(acc[m][n][3] + bBv, 0.f) * wBv;
        }
        s0 += __shfl_xor_sync(0xffffffffu, s0, 1);
        s0 += __shfl_xor_sync(0xffffffffu, s0, 2);
        s1 += __shfl_xor_sync(0xffffffffu, s1, 1);
        s1 += __shfl_xor_sync(0xffffffffu, s1, 2);
        if (tg == 0) {
            int r0 = wy * 32 + m * 16 + g;
            red[(iW * 128 + r0) * 2 + wx]     = s0;
            red[(iW * 128 + r0 + 8) * 2 + wx] = s1;
        }
    }
    __syncthreads();

    if (tid < 256) {
        int i  = tid >> 7;
        int jj = tid & 127;
        const float* rp = &red[(i * 128 + jj) * 2];
        float sum = rp[0] + rp[1] + b3v;
        int iG = i0 + i, j = j0 + jj;
        bool valid = (j >= iG + 2) && ((j - iG) != (NN - 1));
        outm[((size_t)(b * NN + iG)) * NN + j] = valid ? tanhf(sum) : 0.f;
    }
}

// ---------------------------------------------------------------------------
// Launcher
// ---------------------------------------------------------------------------
extern "C" void kernel_launch(void* const* d_in, const int* in_sizes, int n_in,
                              void* d_out, int out_size) {
    const float* x  = (const float*)d_in[0];
    const float* W1 = (const float*)d_in[1];
    const float* b1 = (const float*)d_in[2];
    const float* W2 = (const float*)d_in[3];
    const float* b2 = (const float*)d_in[4];
    const float* W3 = (const float*)d_in[5];
    const float* b3 = (const float*)d_in[6];
    float* out = (float*)d_out;

    const int MAT  = BB * NN * NN;   // 524288
    const int TOUR = BB * NN;        // 2048

    size_t matOff = 0;
    bool hasTour = false;
    if (out_size >= MAT + TOUR) { hasTour = true; matOff = (size_t)out_size - MAT; }

    cudaFuncSetAttribute(pair_kernel, cudaFuncAttributeMaxDynamicSharedMemorySize,
                         SMEM_BYTES);

    cudaMemsetAsync(d_out, 0, (size_t)out_size * sizeof(float), 0);
    if (hasTour) tour_kernel<<<(TOUR + 255) / 256, 256>>>(out);

    proj_kernel<<<256, 256>>>(x, W1, b1);
    w2prep_kernel<<<128, 256>>>(W2);
    pair_kernel<<<BB * 128 * 2, 512, SMEM_BYTES>>>(b2, W3, b3, out + matOff);
}

// round 12
// speedup vs baseline: 1.8267x; 1.0162x over previous
#include <cuda_runtime.h>
#include <cuda_fp16.h>
#include <cstdint>

// Problem shape (fixed)
#define BB 8
#define NN 256
#define DD 128
#define KK 256   // 2*D

// Scratch (half: mantissa == tf32, range safe for O(1) data)
__device__ __half g_Pih[BB * NN * KK];   // Pi with b1 folded in
__device__ __half g_Pjh[BB * NN * KK];
__device__ __half g_W2h[DD * KK];        // W2 transposed to [c][k]

// ---------------------------------------------------------------------------
// Helpers
// ---------------------------------------------------------------------------
__device__ __forceinline__ uint32_t h2_as_u32(__half2 h) {
    union { __half2 h; uint32_t u; } cvt;
    cvt.h = h;
    return cvt.u;
}
__device__ __forceinline__ __half2 u32_as_h2(uint32_t u) {
    union { uint32_t u; __half2 h; } cvt;
    cvt.u = u;
    return cvt.h;
}

// fp16 MMA m16n8k16, fp32 accumulate
__device__ __forceinline__ void mma_f16(float* d,
                                        uint32_t a0, uint32_t a1, uint32_t a2, uint32_t a3,
                                        uint32_t b0, uint32_t b1) {
    asm volatile(
        "mma.sync.aligned.m16n8k16.row.col.f32.f16.f16.f32 "
        "{%0,%1,%2,%3}, {%4,%5,%6,%7}, {%8,%9}, {%0,%1,%2,%3};"
        : "+f"(d[0]), "+f"(d[1]), "+f"(d[2]), "+f"(d[3])
        : "r"(a0), "r"(a1), "r"(a2), "r"(a3), "r"(b0), "r"(b1));
}

// ldmatrix 4x m8n8 b16 tiles
__device__ __forceinline__ void ldx4(uint32_t* r, uint32_t addr) {
    asm volatile(
        "ldmatrix.sync.aligned.m8n8.x4.shared.b16 {%0,%1,%2,%3}, [%4];"
        : "=r"(r[0]), "=r"(r[1]), "=r"(r[2]), "=r"(r[3]) : "r"(addr));
}

// ---------------------------------------------------------------------------
// Tour output
// ---------------------------------------------------------------------------
__global__ void tour_kernel(float* __restrict__ out) {
    int idx = blockIdx.x * 256 + threadIdx.x;
    if (idx < BB * NN) out[idx] = (float)(idx & (NN - 1));
}

// ---------------------------------------------------------------------------
// Projection kernel (fp32 math, half output)
// ---------------------------------------------------------------------------
__global__ __launch_bounds__(256) void proj_kernel(const float* __restrict__ x,
                                                   const float* __restrict__ W1,
                                                   const float* __restrict__ b1) {
    int blk = blockIdx.x;
    int b   = blk >> 5;
    int n0  = (blk & 31) * 8;

    __shared__ float xs[9][DD];
    for (int t = threadIdx.x; t < 9 * DD; t += 256) {
        int r = t / DD, d = t % DD;
        int n = (n0 + r) & (NN - 1);
        xs[r][d] = x[((size_t)b * NN + n) * DD + d];
    }
    __syncthreads();

    int c = threadIdx.x;
    float accPi[8], accPj[8];
#pragma unroll
    for (int r = 0; r < 8; r++) { accPi[r] = 0.f; accPj[r] = 0.f; }

#pragma unroll 4
    for (int d = 0; d < DD; d++) {
        float wa = W1[(0 * DD + d) * KK + c];
        float wb = W1[(1 * DD + d) * KK + c];
        float wc = W1[(2 * DD + d) * KK + c];
        float wd = W1[(3 * DD + d) * KK + c];
#pragma unroll
        for (int r = 0; r < 8; r++) {
            float xv  = xs[r][d];
            float xnv = xs[r + 1][d];
            accPi[r] += xv * wa + xnv * wb;
            accPj[r] += xv * wc + xnv * wd;
        }
    }
    float b1c = b1[c];
#pragma unroll
    for (int r = 0; r < 8; r++) {
        int n = n0 + r;
        size_t off = ((size_t)b * NN + n) * KK + c;
        g_Pih[off] = __float2half_rn(accPi[r] + b1c);
        g_Pjh[off] = __float2half_rn(accPj[r]);
    }
}

// ---------------------------------------------------------------------------
// W2 prep: transpose [k][c] fp32 -> [c][k] half
// ---------------------------------------------------------------------------
__global__ void w2prep_kernel(const float* __restrict__ W2) {
    int idx = blockIdx.x * 256 + threadIdx.x;  // k*128 + c
    int k = idx >> 7, c = idx & 127;
    g_W2h[c * KK + k] = __float2half_rn(W2[idx]);
}

// ---------------------------------------------------------------------------
// Pair kernel: CTA = (b, {i0,i0+1}, j-tile of 128), fp16 m16n8k16.
// 512 thr = 16 warps = 2(i) x 4(wy: j 32-range) x 2(wx: c 64-range).
// Pj fragments ALSO via ldmatrix (1 LDSM replaces 4 LDS.32 per m-half);
// A built in registers (hadd2+hmax2); NO barriers in the K loop; unroll 4.
// ---------------------------------------------------------------------------
#define BROW 264                       // half stride: 256+8 (conflict-free)

// byte offsets in dynamic smem
#define OFF_BH   0                     // 128*264*2 = 67584
#define OFF_PJ   67584                 // 128*264*2 = 67584
#define OFF_PI   135168                // 512*2     = 1024
#define OFF_B2   136192                // 512
#define OFF_W3   136704                // 512
#define OFF_RED  137216                // 2*128*2*4 = 2048
#define SMEM_BYTES 139264

__global__ __launch_bounds__(512, 1) void pair_kernel(const float* __restrict__ b2g,
                                                      const float* __restrict__ w3g,
                                                      const float* __restrict__ b3g,
                                                      float* __restrict__ outm) {
    extern __shared__ char smem[];
    __half* Bh  = (__half*)(smem + OFF_BH);
    __half* Pjs = (__half*)(smem + OFF_PJ);
    __half* Pis = (__half*)(smem + OFF_PI);
    float*  b2s = (float*)(smem + OFF_B2);
    float*  w3s = (float*)(smem + OFF_W3);
    float*  red = (float*)(smem + OFF_RED);

    int tid  = threadIdx.x;
    int lane = tid & 31, wid = tid >> 5;
    int iW = wid & 1;                  // which i this warp handles
    int wy = (wid >> 1) & 3;           // j 32-range
    int wx = wid >> 3;                 // c 64-range (0..1)
    int g  = lane >> 2, tg = lane & 3;

    int bid = blockIdx.x;
    int jt = bid & 1;
    int ig = (bid >> 1) & 127;
    int b  = bid >> 8;
    int j0 = jt << 7, i0 = ig << 1;
    if (i0 > j0 + 125) return;         // fully masked tile (output zeroed by memset)

    // Prologue: W2 image, Pj j-tile, Pi rows, b2, W3
    {
        const uint4* wsrc = (const uint4*)g_W2h;
#pragma unroll
        for (int q = tid; q < 4096; q += 512) {
            int cc = q >> 5, qq = q & 31;
            *(uint4*)&Bh[cc * BROW + qq * 8] = wsrc[cc * 32 + qq];
        }
        const uint4* psrc = (const uint4*)&g_Pjh[(size_t)(b * NN + j0) * KK];
#pragma unroll
        for (int q = tid; q < 4096; q += 512) {
            int jj = q >> 5, qq = q & 31;
            *(uint4*)&Pjs[jj * BROW + qq * 8] = psrc[jj * 32 + qq];
        }
        const __half* pisrc = &g_Pih[(size_t)(b * NN + i0) * KK];
        Pis[tid] = pisrc[tid];          // 512 halves = both i rows
        if (tid < 128) { b2s[tid] = b2g[tid]; w3s[tid] = w3g[tid]; }
    }
    __syncthreads();   // the only barrier before the epilogue

    float acc[2][8][4];
#pragma unroll
    for (int m = 0; m < 2; m++)
#pragma unroll
        for (int n = 0; n < 8; n++)
#pragma unroll
            for (int q = 0; q < 4; q++) acc[m][n][q] = 0.f;

    // ldmatrix lane addresses (bytes)
    uint32_t BhAddr = (uint32_t)__cvta_generic_to_shared(Bh);
    uint32_t PjAddr = (uint32_t)__cvta_generic_to_shared(Pjs);
    int rowL = lane & 15, kL = (lane >> 4) * 8;
    uint32_t bAddr[4];
#pragma unroll
    for (int t = 0; t < 4; t++)
        bAddr[t] = (uint32_t)((wx * 64 + t * 16 + rowL) * BROW + kL) * 2 + BhAddr;
    uint32_t pjAddr[2];
#pragma unroll
    for (int mh = 0; mh < 2; mh++)
        pjAddr[mh] = (uint32_t)((wy * 32 + mh * 16 + rowL) * BROW + kL) * 2 + PjAddr;

    const __half2 zero2 = __float2half2_rn(0.f);
    const __half* PiRow = &Pis[iW * 256];

#pragma unroll 4
    for (int c = 0; c < 16; c++) {
        int k0 = c << 4;

        // B fragments: 4x ldmatrix.x4 -> 8 (b0,b1) pairs covering 64 c
        uint32_t bq[4][4];
#pragma unroll
        for (int t = 0; t < 4; t++) ldx4(bq[t], bAddr[t] + (uint32_t)k0 * 2);

        // Pi half2 (broadcast loads, this warp's i only)
        __half2 pil = *(const __half2*)&PiRow[k0 + 2 * tg];
        __half2 pih = *(const __half2*)&PiRow[k0 + 2 * tg + 8];

#pragma unroll
        for (int mh = 0; mh < 2; mh++) {
            // Pj fragment: one ldmatrix.x4 delivers (a0,a1,a2,a3) layout
            uint32_t pq[4];
            ldx4(pq, pjAddr[mh] + (uint32_t)k0 * 2);
            uint32_t a0 = h2_as_u32(__hmax2(__hadd2(u32_as_h2(pq[0]), pil), zero2));
            uint32_t a1 = h2_as_u32(__hmax2(__hadd2(u32_as_h2(pq[1]), pil), zero2));
            uint32_t a2 = h2_as_u32(__hmax2(__hadd2(u32_as_h2(pq[2]), pih), zero2));
            uint32_t a3 = h2_as_u32(__hmax2(__hadd2(u32_as_h2(pq[3]), pih), zero2));
#pragma unroll
            for (int t = 0; t < 4; t++) {
                mma_f16(acc[mh][2 * t],     a0, a1, a2, a3, bq[t][0], bq[t][2]);
                mma_f16(acc[mh][2 * t + 1], a0, a1, a2, a3, bq[t][1], bq[t][3]);
            }
        }
    }

    // Epilogue: relu(C+b2).W3 partial dots, shfl reduce over tg, smem over wx
    float b3v = b3g[0];
#pragma unroll
    for (int m = 0; m < 2; m++) {
        float s0 = 0.f, s1 = 0.f;
#pragma unroll
        for (int n = 0; n < 8; n++) {
            int c0 = wx * 64 + n * 8 + tg * 2;
            float bA  = b2s[c0],     wA  = w3s[c0];
            float bBv = b2s[c0 + 1], wBv = w3s[c0 + 1];
            s0 += fmaxf(acc[m][n][0] + bA, 0.f) * wA
                + fmaxf(acc[m][n][1] + bBv, 0.f) * wBv;
            s1 += fmaxf(acc[m][n][2] + bA, 0.f) * wA
                + fmaxf(acc[m][n][3] + bBv, 0.f) * wBv;
        }
        s0 += __shfl_xor_sync(0xffffffffu, s0, 1);
        s0 += __shfl_xor_sync(0xffffffffu, s0, 2);
        s1 += __shfl_xor_sync(0xffffffffu, s1, 1);
        s1 += __shfl_xor_sync(0xffffffffu, s1, 2);
        if (tg == 0) {
            int r0 = wy * 32 + m * 16 + g;
            red[(iW * 128 + r0) * 2 + wx]     = s0;
            red[(iW * 128 + r0 + 8) * 2 + wx] = s1;
        }
    }
    __syncthreads();

    if (tid < 256) {
        int i  = tid >> 7;
        int jj = tid & 127;
        const float* rp = &red[(i * 128 + jj) * 2];
        float sum = rp[0] + rp[1] + b3v;
        int iG = i0 + i, j = j0 + jj;
        bool valid = (j >= iG + 2) && ((j - iG) != (NN - 1));
        outm[((size_t)(b * NN + iG)) * NN + j] = valid ? tanhf(sum) : 0.f;
    }
}

// ---------------------------------------------------------------------------
// Launcher
// ---------------------------------------------------------------------------
extern "C" void kernel_launch(void* const* d_in, const int* in_sizes, int n_in,
                              void* d_out, int out_size) {
    const float* x  = (const float*)d_in[0];
    const float* W1 = (const float*)d_in[1];
    const float* b1 = (const float*)d_in[2];
    const float* W2 = (const float*)d_in[3];
    const float* b2 = (const float*)d_in[4];
    const float* W3 = (const float*)d_in[5];
    const float* b3 = (const float*)d_in[6];
    float* out = (float*)d_out;

    const int MAT  = BB * NN * NN;   // 524288
    const int TOUR = BB * NN;        // 2048

    size_t matOff = 0;
    bool hasTour = false;
    if (out_size >= MAT + TOUR) { hasTour = true; matOff = (size_t)out_size - MAT; }

    cudaFuncSetAttribute(pair_kernel, cudaFuncAttributeMaxDynamicSharedMemorySize,
                         SMEM_BYTES);

    cudaMemsetAsync(d_out, 0, (size_t)out_size * sizeof(float), 0);
    if (hasTour) tour_kernel<<<(TOUR + 255) / 256, 256>>>(out);

    proj_kernel<<<256, 256>>>(x, W1, b1);
    w2prep_kernel<<<128, 256>>>(W2);
    pair_kernel<<<BB * 128 * 2, 512, SMEM_BYTES>>>(b2, W3, b3, out + matOff);
}

// round 13
// speedup vs baseline: 1.9979x; 1.0937x over previous
#include <cuda_runtime.h>
#include <cuda_fp16.h>
#include <cstdint>

// Problem shape (fixed)
#define BB 8
#define NN 256
#define DD 128
#define KK 256   // 2*D

// Scratch (half: mantissa == tf32, range safe for O(1) data)
__device__ __half g_Pih[BB * NN * KK];   // Pi with b1 folded in
__device__ __half g_Pjh[BB * NN * KK];
__device__ __half g_W2h[DD * KK];        // W2 transposed to [c][k]

// ---------------------------------------------------------------------------
// Helpers
// ---------------------------------------------------------------------------
__device__ __forceinline__ uint32_t h2_as_u32(__half2 h) {
    union { __half2 h; uint32_t u; } cvt;
    cvt.h = h;
    return cvt.u;
}
__device__ __forceinline__ __half2 u32_as_h2(uint32_t u) {
    union { uint32_t u; __half2 h; } cvt;
    cvt.u = u;
    return cvt.h;
}

// fp16 MMA m16n8k16, fp32 accumulate
__device__ __forceinline__ void mma_f16(float* d,
                                        uint32_t a0, uint32_t a1, uint32_t a2, uint32_t a3,
                                        uint32_t b0, uint32_t b1) {
    asm volatile(
        "mma.sync.aligned.m16n8k16.row.col.f32.f16.f16.f32 "
        "{%0,%1,%2,%3}, {%4,%5,%6,%7}, {%8,%9}, {%0,%1,%2,%3};"
        : "+f"(d[0]), "+f"(d[1]), "+f"(d[2]), "+f"(d[3])
        : "r"(a0), "r"(a1), "r"(a2), "r"(a3), "r"(b0), "r"(b1));
}

// ldmatrix 4x m8n8 b16 tiles
__device__ __forceinline__ void ldx4(uint32_t* r, uint32_t addr) {
    asm volatile(
        "ldmatrix.sync.aligned.m8n8.x4.shared.b16 {%0,%1,%2,%3}, [%4];"
        : "=r"(r[0]), "=r"(r[1]), "=r"(r[2]), "=r"(r[3]) : "r"(addr));
}

// ---------------------------------------------------------------------------
// Tour output
// ---------------------------------------------------------------------------
__global__ void tour_kernel(float* __restrict__ out) {
    int idx = blockIdx.x * 256 + threadIdx.x;
    if (idx < BB * NN) out[idx] = (float)(idx & (NN - 1));
}

// ---------------------------------------------------------------------------
// Projection kernel (fp32 math, half output)
// ---------------------------------------------------------------------------
__global__ __launch_bounds__(256) void proj_kernel(const float* __restrict__ x,
                                                   const float* __restrict__ W1,
                                                   const float* __restrict__ b1) {
    int blk = blockIdx.x;
    int b   = blk >> 5;
    int n0  = (blk & 31) * 8;

    __shared__ float xs[9][DD];
    for (int t = threadIdx.x; t < 9 * DD; t += 256) {
        int r = t / DD, d = t % DD;
        int n = (n0 + r) & (NN - 1);
        xs[r][d] = x[((size_t)b * NN + n) * DD + d];
    }
    __syncthreads();

    int c = threadIdx.x;
    float accPi[8], accPj[8];
#pragma unroll
    for (int r = 0; r < 8; r++) { accPi[r] = 0.f; accPj[r] = 0.f; }

#pragma unroll 4
    for (int d = 0; d < DD; d++) {
        float wa = W1[(0 * DD + d) * KK + c];
        float wb = W1[(1 * DD + d) * KK + c];
        float wc = W1[(2 * DD + d) * KK + c];
        float wd = W1[(3 * DD + d) * KK + c];
#pragma unroll
        for (int r = 0; r < 8; r++) {
            float xv  = xs[r][d];
            float xnv = xs[r + 1][d];
            accPi[r] += xv * wa + xnv * wb;
            accPj[r] += xv * wc + xnv * wd;
        }
    }
    float b1c = b1[c];
#pragma unroll
    for (int r = 0; r < 8; r++) {
        int n = n0 + r;
        size_t off = ((size_t)b * NN + n) * KK + c;
        g_Pih[off] = __float2half_rn(accPi[r] + b1c);
        g_Pjh[off] = __float2half_rn(accPj[r]);
    }
}

// ---------------------------------------------------------------------------
// W2 prep: transpose [k][c] fp32 -> [c][k] half
// ---------------------------------------------------------------------------
__global__ void w2prep_kernel(const float* __restrict__ W2) {
    int idx = blockIdx.x * 256 + threadIdx.x;  // k*128 + c
    int k = idx >> 7, c = idx & 127;
    g_W2h[c * KK + k] = __float2half_rn(W2[idx]);
}

// ---------------------------------------------------------------------------
// Pair kernel: CTA = (b, {i0,i0+1}, j-tile of 128), fp16 m16n8k16.
// 512 thr = 16 warps: iW = wid&1 (i), wx = (wid>>1)&1 (c 64-range),
// wy = wid>>2 (j 32-range)  -> each SMSP (wid%4) holds wy = 0,1,2,3
// so the mask-skip load is balanced across schedulers.
// MASK SKIP: a 16-row j-block entirely below i+2 is skipped (no Pj LDSM,
// no MMAs); if both halves masked the warp skips the whole mainloop.
// ---------------------------------------------------------------------------
#define BROW 264                       // half stride: 256+8 (conflict-free)

// byte offsets in dynamic smem
#define OFF_BH   0                     // 128*264*2 = 67584
#define OFF_PJ   67584                 // 128*264*2 = 67584
#define OFF_PI   135168                // 512*2     = 1024
#define OFF_B2   136192                // 512
#define OFF_W3   136704                // 512
#define OFF_RED  137216                // 2*128*2*4 = 2048
#define SMEM_BYTES 139264

__global__ __launch_bounds__(512, 1) void pair_kernel(const float* __restrict__ b2g,
                                                      const float* __restrict__ w3g,
                                                      const float* __restrict__ b3g,
                                                      float* __restrict__ outm) {
    extern __shared__ char smem[];
    __half* Bh  = (__half*)(smem + OFF_BH);
    __half* Pjs = (__half*)(smem + OFF_PJ);
    __half* Pis = (__half*)(smem + OFF_PI);
    float*  b2s = (float*)(smem + OFF_B2);
    float*  w3s = (float*)(smem + OFF_W3);
    float*  red = (float*)(smem + OFF_RED);

    int tid  = threadIdx.x;
    int lane = tid & 31, wid = tid >> 5;
    int iW = wid & 1;                  // which i this warp handles
    int wx = (wid >> 1) & 1;           // c 64-range
    int wy = wid >> 2;                 // j 32-range: one of each per SMSP
    int g  = lane >> 2, tg = lane & 3;

    int bid = blockIdx.x;
    int jt = bid & 1;
    int ig = (bid >> 1) & 127;
    int b  = bid >> 8;
    int j0 = jt << 7, i0 = ig << 1;
    if (i0 > j0 + 125) return;         // fully masked tile (output zeroed by memset)

    int iMe = i0 + iW;
    // 16-row block validity: block [jblk, jblk+16) has a valid j iff jblk+15 >= i+2
    bool ok0 = (j0 + wy * 32 + 15) >= iMe + 2;
    bool ok1 = (j0 + wy * 32 + 31) >= iMe + 2;

    // Prologue: W2 image, Pj j-tile, Pi rows, b2, W3
    {
        const uint4* wsrc = (const uint4*)g_W2h;
#pragma unroll
        for (int q = tid; q < 4096; q += 512) {
            int cc = q >> 5, qq = q & 31;
            *(uint4*)&Bh[cc * BROW + qq * 8] = wsrc[cc * 32 + qq];
        }
        const uint4* psrc = (const uint4*)&g_Pjh[(size_t)(b * NN + j0) * KK];
#pragma unroll
        for (int q = tid; q < 4096; q += 512) {
            int jj = q >> 5, qq = q & 31;
            *(uint4*)&Pjs[jj * BROW + qq * 8] = psrc[jj * 32 + qq];
        }
        const __half* pisrc = &g_Pih[(size_t)(b * NN + i0) * KK];
        Pis[tid] = pisrc[tid];          // 512 halves = both i rows
        if (tid < 128) { b2s[tid] = b2g[tid]; w3s[tid] = w3g[tid]; }
    }
    __syncthreads();   // the only barrier before the epilogue

    float acc[2][8][4];
#pragma unroll
    for (int m = 0; m < 2; m++)
#pragma unroll
        for (int n = 0; n < 8; n++)
#pragma unroll
            for (int q = 0; q < 4; q++) acc[m][n][q] = 0.f;

    if (ok0 || ok1) {
        // ldmatrix lane addresses (bytes)
        uint32_t BhAddr = (uint32_t)__cvta_generic_to_shared(Bh);
        uint32_t PjAddr = (uint32_t)__cvta_generic_to_shared(Pjs);
        int rowL = lane & 15, kL = (lane >> 4) * 8;
        uint32_t bAddr[4];
#pragma unroll
        for (int t = 0; t < 4; t++)
            bAddr[t] = (uint32_t)((wx * 64 + t * 16 + rowL) * BROW + kL) * 2 + BhAddr;
        uint32_t pjAddr[2];
#pragma unroll
        for (int mh = 0; mh < 2; mh++)
            pjAddr[mh] = (uint32_t)((wy * 32 + mh * 16 + rowL) * BROW + kL) * 2 + PjAddr;

        const __half2 zero2 = __float2half2_rn(0.f);
        const __half* PiRow = &Pis[iW * 256];

#pragma unroll 4
        for (int c = 0; c < 16; c++) {
            int k0 = c << 4;

            // B fragments: 4x ldmatrix.x4 -> 8 (b0,b1) pairs covering 64 c
            uint32_t bq[4][4];
#pragma unroll
            for (int t = 0; t < 4; t++) ldx4(bq[t], bAddr[t] + (uint32_t)k0 * 2);

            // Pi half2 (broadcast loads, this warp's i only)
            __half2 pil = *(const __half2*)&PiRow[k0 + 2 * tg];
            __half2 pih = *(const __half2*)&PiRow[k0 + 2 * tg + 8];

#pragma unroll
            for (int mh = 0; mh < 2; mh++) {
                if (mh == 0 ? !ok0 : !ok1) continue;   // masked 16-row block
                uint32_t pq[4];
                ldx4(pq, pjAddr[mh] + (uint32_t)k0 * 2);
                uint32_t a0 = h2_as_u32(__hmax2(__hadd2(u32_as_h2(pq[0]), pil), zero2));
                uint32_t a1 = h2_as_u32(__hmax2(__hadd2(u32_as_h2(pq[1]), pil), zero2));
                uint32_t a2 = h2_as_u32(__hmax2(__hadd2(u32_as_h2(pq[2]), pih), zero2));
                uint32_t a3 = h2_as_u32(__hmax2(__hadd2(u32_as_h2(pq[3]), pih), zero2));
#pragma unroll
                for (int t = 0; t < 4; t++) {
                    mma_f16(acc[mh][2 * t],     a0, a1, a2, a3, bq[t][0], bq[t][2]);
                    mma_f16(acc[mh][2 * t + 1], a0, a1, a2, a3, bq[t][1], bq[t][3]);
                }
            }
        }
    }

    // Epilogue: relu(C+b2).W3 partial dots, shfl reduce over tg, smem over wx
    float b3v = b3g[0];
#pragma unroll
    for (int m = 0; m < 2; m++) {
        float s0 = 0.f, s1 = 0.f;
#pragma unroll
        for (int n = 0; n < 8; n++) {
            int c0 = wx * 64 + n * 8 + tg * 2;
            float bA  = b2s[c0],     wA  = w3s[c0];
            float bBv = b2s[c0 + 1], wBv = w3s[c0 + 1];
            s0 += fmaxf(acc[m][n][0] + bA, 0.f) * wA
                + fmaxf(acc[m][n][1] + bBv, 0.f) * wBv;
            s1 += fmaxf(acc[m][n][2] + bA, 0.f) * wA
                + fmaxf(acc[m][n][3] + bBv, 0.f) * wBv;
        }
        s0 += __shfl_xor_sync(0xffffffffu, s0, 1);
        s0 += __shfl_xor_sync(0xffffffffu, s0, 2);
        s1 += __shfl_xor_sync(0xffffffffu, s1, 1);
        s1 += __shfl_xor_sync(0xffffffffu, s1, 2);
        if (tg == 0) {
            int r0 = wy * 32 + m * 16 + g;
            red[(iW * 128 + r0) * 2 + wx]     = s0;
            red[(iW * 128 + r0 + 8) * 2 + wx] = s1;
        }
    }
    __syncthreads();

    if (tid < 256) {
        int i  = tid >> 7;
        int jj = tid & 127;
        const float* rp = &red[(i * 128 + jj) * 2];
        float sum = rp[0] + rp[1] + b3v;
        int iG = i0 + i, j = j0 + jj;
        bool valid = (j >= iG + 2) && ((j - iG) != (NN - 1));
        outm[((size_t)(b * NN + iG)) * NN + j] = valid ? tanhf(sum) : 0.f;
    }
}

// ---------------------------------------------------------------------------
// Launcher
// ---------------------------------------------------------------------------
extern "C" void kernel_launch(void* const* d_in, const int* in_sizes, int n_in,
                              void* d_out, int out_size) {
    const float* x  = (const float*)d_in[0];
    const float* W1 = (const float*)d_in[1];
    const float* b1 = (const float*)d_in[2];
    const float* W2 = (const float*)d_in[3];
    const float* b2 = (const float*)d_in[4];
    const float* W3 = (const float*)d_in[5];
    const float* b3 = (const float*)d_in[6];
    float* out = (float*)d_out;

    const int MAT  = BB * NN * NN;   // 524288
    const int TOUR = BB * NN;        // 2048

    size_t matOff = 0;
    bool hasTour = false;
    if (out_size >= MAT + TOUR) { hasTour = true; matOff = (size_t)out_size - MAT; }

    cudaFuncSetAttribute(pair_kernel, cudaFuncAttributeMaxDynamicSharedMemorySize,
                         SMEM_BYTES);

    cudaMemsetAsync(d_out, 0, (size_t)out_size * sizeof(float), 0);
    if (hasTour) tour_kernel<<<(TOUR + 255) / 256, 256>>>(out);

    proj_kernel<<<256, 256>>>(x, W1, b1);
    w2prep_kernel<<<128, 256>>>(W2);
    pair_kernel<<<BB * 128 * 2, 512, SMEM_BYTES>>>(b2, W3, b3, out + matOff);
}